// round 17
// baseline (speedup 1.0000x reference)
#include <cuda_runtime.h>
#include <cuda_fp16.h>
#include <math.h>
#include <stdint.h>

#define D_MODEL   1024
#define NUM_HEADS 16
#define DKH       64
#define BATCH     2
#define SEQ       2048
#define MROWS     (BATCH * SEQ)   // 4096

// Q pre-scale: 1/sqrt(dk) * log2(e)  (softmax runs in exp2 domain)
#define QSCALE (0.125f * 1.44269504f)

// ---------------- scratch (device globals; no allocation allowed) ----------
__device__ __half g_X16[MROWS * D_MODEL];
__device__ __half g_O16[MROWS * D_MODEL];
__device__ __half g_Q16[MROWS * D_MODEL];
__device__ __half g_K16[MROWS * D_MODEL];
__device__ __half g_V16[MROWS * D_MODEL];
__device__ __half g_W16[4 * D_MODEL * D_MODEL];

// ---------------- helpers ---------------------------------------------------
__device__ __forceinline__ uint32_t s_u32(const void* p) {
    return (uint32_t)__cvta_generic_to_shared(p);
}

#define LDSM4(r0, r1, r2, r3, a)                                              \
    asm volatile("ldmatrix.sync.aligned.m8n8.x4.shared.b16 {%0,%1,%2,%3},[%4];"\
        : "=r"(r0), "=r"(r1), "=r"(r2), "=r"(r3) : "r"(a))

#define LDSM4T(r0, r1, r2, r3, a)                                             \
    asm volatile("ldmatrix.sync.aligned.m8n8.x4.trans.shared.b16 {%0,%1,%2,%3},[%4];"\
        : "=r"(r0), "=r"(r1), "=r"(r2), "=r"(r3) : "r"(a))

// fp32-accum HMMA
#define MMA_FP16(c, a, b)                                                     \
    asm("mma.sync.aligned.m16n8k16.row.col.f32.f16.f16.f32 "                  \
        "{%0,%1,%2,%3}, {%4,%5,%6,%7}, {%8,%9}, {%0,%1,%2,%3};"               \
        : "+f"((c)[0]), "+f"((c)[1]), "+f"((c)[2]), "+f"((c)[3])              \
        : "r"((a)[0]), "r"((a)[1]), "r"((a)[2]), "r"((a)[3]),                 \
          "r"((b)[0]), "r"((b)[1]))

// fp16-accum HMMA (C/D = 2 packed half2 regs)
#define MMA_FP16_H(c, a, b)                                                   \
    asm("mma.sync.aligned.m16n8k16.row.col.f16.f16.f16.f16 "                  \
        "{%0,%1}, {%2,%3,%4,%5}, {%6,%7}, {%0,%1};"                           \
        : "+r"((c)[0]), "+r"((c)[1])                                          \
        : "r"((a)[0]), "r"((a)[1]), "r"((a)[2]), "r"((a)[3]),                 \
          "r"((b)[0]), "r"((b)[1]))

#define CP_ASYNC16(dst, src)                                                  \
    asm volatile("cp.async.cg.shared.global [%0], [%1], 16;"                  \
        :: "r"(dst), "l"(src))
#define CP_COMMIT   asm volatile("cp.async.commit_group;")
#define CP_WAIT0    asm volatile("cp.async.wait_group 0;")

__device__ __forceinline__ float ex2f(float x) {
    float r;
    asm("ex2.approx.f32 %0, %1;" : "=f"(r) : "f"(x));
    return r;
}

__device__ __forceinline__ uint32_t h2ex2(uint32_t a) {
    uint32_t d;
    asm("ex2.approx.f16x2 %0, %1;" : "=r"(d) : "r"(a));
    return d;
}

__device__ __forceinline__ uint32_t hadd2(uint32_t a, uint32_t b) {
    uint32_t d;
    asm("add.f16x2 %0, %1, %2;" : "=r"(d) : "r"(a), "r"(b));
    return d;
}

__device__ __forceinline__ uint32_t hmax2(uint32_t a, uint32_t b) {
    uint32_t d;
    asm("max.f16x2 %0, %1, %2;" : "=r"(d) : "r"(a), "r"(b));
    return d;
}

__device__ __forceinline__ uint32_t f2h2(float a, float b) {
    __half2 h = __floats2half2_rn(a, b);
    return *reinterpret_cast<uint32_t*>(&h);
}

// ============================================================================
// converters
// ============================================================================
__global__ void convert_h4(const float4* __restrict__ src,
                           uint2* __restrict__ dst, int n4)
{
    int i = blockIdx.x * blockDim.x + threadIdx.x;
    if (i >= n4) return;
    float4 v = src[i];
    uint2 d;
    d.x = f2h2(v.x, v.y);
    d.y = f2h2(v.z, v.w);
    dst[i] = d;
}

__global__ void convert_weights4(const float4* __restrict__ w0,
                                 const float4* __restrict__ w1,
                                 const float4* __restrict__ w2,
                                 const float4* __restrict__ w3,
                                 uint2* __restrict__ W, int n4)
{
    int i = blockIdx.x * blockDim.x + threadIdx.x;
    if (i >= n4) return;
    int z = blockIdx.y;
    const float4* src = (z == 0) ? w0 : (z == 1) ? w1 : (z == 2) ? w2 : w3;
    float4 v = src[i];
    uint2 d;
    d.x = f2h2(v.x, v.y);
    d.y = f2h2(v.z, v.w);
    W[(size_t)z * n4 + i] = d;
}

// ============================================================================
// fp16 GEMM: C = A @ W^T + bias. 128x128 tile, BK=64, 8 warps,
// cp.async double buffer (single barrier per iter), fp32 accum.
// ============================================================================
#define GSTR    72
#define G_ARR   (128 * GSTR)
#define G_STAGE (2 * G_ARR)
#define GEMM_SMEM (2 * G_STAGE * 2)   // 73728 bytes

__device__ __forceinline__ void gemm_prefetch(
    __half* st, const __half* __restrict__ A, const __half* __restrict__ W,
    int rowBase, int colBase, int kt, int tid)
{
#pragma unroll
    for (int p = 0; p < 4; p++) {
        int id = tid + p * 256;
        int r  = id >> 3;
        int q  = (id & 7) * 8;
        int so = r * GSTR + q;
        CP_ASYNC16(s_u32(st + so),
                   A + (size_t)(rowBase + r) * D_MODEL + kt + q);
        CP_ASYNC16(s_u32(st + G_ARR + so),
                   W + (size_t)(colBase + r) * D_MODEL + kt + q);
    }
}

__device__ __forceinline__ void gemm_body(
    const __half* __restrict__ A, const __half* __restrict__ W,
    const float* __restrict__ bias, float* __restrict__ C,
    __half* __restrict__ D, int mode, __half* sm)
{
    const int tid  = threadIdx.x;
    const int lane = tid & 31;
    const int wrp  = tid >> 5;
    const int g    = lane >> 2;
    const int t    = lane & 3;
    const int wm   = (wrp & 1) * 64;
    const int wn   = (wrp >> 1) * 32;
    const int rowBase = blockIdx.y * 128;
    const int colBase = blockIdx.x * 128;

    const int arow = (lane & 15);
    const int akoA = ((lane >> 4) << 3);
    const int brow = ((lane >> 4) << 3) + (lane & 7);
    const int bkoB = ((lane >> 3) & 1) * 8;

    float c[4][4][4];
#pragma unroll
    for (int i = 0; i < 4; i++)
#pragma unroll
        for (int j = 0; j < 4; j++)
#pragma unroll
            for (int e = 0; e < 4; e++) c[i][j][e] = 0.0f;

    gemm_prefetch(sm, A, W, rowBase, colBase, 0, tid);
    CP_COMMIT;

    const int NK = D_MODEL / 64;
    for (int it = 0; it < NK; it++) {
        CP_WAIT0;
        __syncthreads();
        if (it + 1 < NK) {
            gemm_prefetch(sm + ((it + 1) & 1) * G_STAGE, A, W,
                          rowBase, colBase, (it + 1) * 64, tid);
            CP_COMMIT;
        }

        __half* st = sm + (it & 1) * G_STAGE;
        __half* sA = st;
        __half* sW = st + G_ARR;

#pragma unroll
        for (int kk = 0; kk < 4; kk++) {
            uint32_t ar[4][4], bb[4][2];
#pragma unroll
            for (int i = 0; i < 4; i++) {
                uint32_t a = s_u32(&sA[(wm + 16 * i + arow) * GSTR + kk * 16 + akoA]);
                LDSM4(ar[i][0], ar[i][1], ar[i][2], ar[i][3], a);
            }
#pragma unroll
            for (int jj = 0; jj < 2; jj++) {
                uint32_t a = s_u32(&sW[(wn + 16 * jj + brow) * GSTR + kk * 16 + bkoB]);
                LDSM4(bb[2*jj][0], bb[2*jj][1], bb[2*jj+1][0], bb[2*jj+1][1], a);
            }
#pragma unroll
            for (int i = 0; i < 4; i++)
#pragma unroll
                for (int j = 0; j < 4; j++) MMA_FP16(c[i][j], ar[i], bb[j]);
        }
    }

    // ---- fused epilogue ----
#pragma unroll
    for (int i = 0; i < 4; i++) {
        int row = rowBase + wm + i * 16 + g;
        int s0  = row & (SEQ - 1);
        int s1  = (row + 8) & (SEQ - 1);
#pragma unroll
        for (int j = 0; j < 4; j++) {
            int col = colBase + wn + j * 8 + 2 * t;
            float b0 = bias[col], b1 = bias[col + 1];
            float x0 = c[i][j][0] + b0, x1 = c[i][j][1] + b1;
            float y0 = c[i][j][2] + b0, y1 = c[i][j][3] + b1;
            size_t i0 = (size_t)row * D_MODEL + col;
            size_t i1 = i0 + (size_t)8 * D_MODEL;
            if (mode == 0) {
                *reinterpret_cast<float2*>(&C[i0]) = make_float2(x0, x1);
                *reinterpret_cast<float2*>(&C[i1]) = make_float2(y0, y1);
            } else if (mode == 3) {
                *(uint32_t*)&D[i0] = f2h2(x0, x1);
                *(uint32_t*)&D[i1] = f2h2(y0, y1);
            } else {
                int p = (col & 63) >> 1;
                float freq = powf(10000.0f, -(float)p * (1.0f / 32.0f));
                float sn0, cs0, sn1, cs1;
                sincosf((float)s0 * freq, &sn0, &cs0);
                sincosf((float)s1 * freq, &sn1, &cs1);
                float r0a = x0 * cs0 - x1 * sn0;
                float r0b = x1 * cs0 + x0 * sn0;
                float r1a = y0 * cs1 - y1 * sn1;
                float r1b = y1 * cs1 + y0 * sn1;
                if (mode == 1) {
                    r0a *= QSCALE; r0b *= QSCALE;
                    r1a *= QSCALE; r1b *= QSCALE;
                }
                *(uint32_t*)&D[i0] = f2h2(r0a, r0b);
                *(uint32_t*)&D[i1] = f2h2(r1a, r1b);
            }
        }
    }
}

__global__ __launch_bounds__(256, 2) void gemm_qkv(
    const __half* __restrict__ A, const __half* __restrict__ WB,
    const float* __restrict__ b0, const float* __restrict__ b1, const float* __restrict__ b2,
    __half* __restrict__ Q16, __half* __restrict__ K16, __half* __restrict__ V16)
{
    extern __shared__ __half smg[];
    const int z = blockIdx.z;
    const size_t WSZ = (size_t)D_MODEL * D_MODEL;
    const float* bias = (z == 0) ? b0 : (z == 1) ? b1 : b2;
    __half* D = (z == 0) ? Q16 : (z == 1) ? K16 : V16;
    gemm_body(A, WB + z * WSZ, bias, (float*)0, D, z + 1, smg);
}

__global__ __launch_bounds__(256, 2) void gemm_out(
    const __half* __restrict__ A, const __half* __restrict__ W,
    const float* __restrict__ bias, float* __restrict__ C)
{
    extern __shared__ __half smg[];
    gemm_body(A, W, bias, C, (__half*)0, 0, smg);
}

// ============================================================================
// Tensor-core flash attention (all fp16):
// S = Q @ K^T (fp32 acc), softmax via ex2.approx.f16x2,
// PV with fp16 accumulators per tile, promoted to fp32 running O.
// Single barrier per tile. occupancy 2.
// ============================================================================
#define ATS     72
#define A_ARR   (64 * ATS)
#define A_STAGE (2 * A_ARR)
#define ATT_SMEM (2 * A_STAGE * 2)        // 36864 bytes

__device__ __forceinline__ void att_prefetch(
    __half* st, const __half* __restrict__ K16, const __half* __restrict__ V16,
    size_t gbase, int kv0, int tid)
{
    int r  = tid >> 2;
    int cq = (tid & 3) * 16;
    int so = r * ATS + cq;
    size_t gk = gbase + (size_t)(kv0 + r) * D_MODEL + cq;
    CP_ASYNC16(s_u32(st + so),             K16 + gk);
    CP_ASYNC16(s_u32(st + so + 8),         K16 + gk + 8);
    CP_ASYNC16(s_u32(st + A_ARR + so),     V16 + gk);
    CP_ASYNC16(s_u32(st + A_ARR + so + 8), V16 + gk + 8);
}

__global__ __launch_bounds__(256, 2) void attention_mma(
    const __half* __restrict__ Q16, const __half* __restrict__ K16,
    const __half* __restrict__ V16, __half* __restrict__ O16)
{
    extern __shared__ __half sKV[];

    const int bh = blockIdx.y;
    const int b  = bh >> 4;
    const int h  = bh & 15;
    const int q0 = blockIdx.x * 128;
    const int tid  = threadIdx.x;
    const int lane = tid & 31;
    const int wrp  = tid >> 5;
    const int g    = lane >> 2;
    const int t    = lane & 3;

    const size_t gbase = (size_t)b * SEQ * D_MODEL + (size_t)h * DKH;

    att_prefetch(sKV, K16, V16, gbase, 0, tid);
    CP_COMMIT;

    // ---- Q fragments directly from gmem (A-frag layout) ----
    uint32_t qf[4][4];
    {
        const int r0 = q0 + 16 * wrp + g;
        size_t ro0 = gbase + (size_t)r0 * D_MODEL;
        size_t ro8 = ro0 + (size_t)8 * D_MODEL;
#pragma unroll
        for (int kc = 0; kc < 4; kc++) {
            int cw = kc * 16 + 2 * t;
            qf[kc][0] = *(const uint32_t*)&Q16[ro0 + cw];
            qf[kc][1] = *(const uint32_t*)&Q16[ro8 + cw];
            qf[kc][2] = *(const uint32_t*)&Q16[ro0 + cw + 8];
            qf[kc][3] = *(const uint32_t*)&Q16[ro8 + cw + 8];
        }
    }

    float m[2] = {-INFINITY, -INFINITY};
    float l[2] = {0.0f, 0.0f};
    float o[8][4];
#pragma unroll
    for (int j = 0; j < 8; j++)
#pragma unroll
        for (int e = 0; e < 4; e++) o[j][e] = 0.0f;

    const int brow  = ((lane >> 4) << 3) + (lane & 7);
    const int bko   = ((lane >> 3) & 1) * 8;
    const int vrow  = (lane & 7) + ((lane >> 3) & 1) * 8;
    const int vcol  = ((lane >> 4) << 3);

    const int NT = SEQ / 64;
    for (int it = 0; it < NT; it++) {
        CP_WAIT0;
        __syncthreads();
        if (it + 1 < NT) {
            att_prefetch(sKV + ((it + 1) & 1) * A_STAGE, K16, V16,
                         gbase, (it + 1) * 64, tid);
            CP_COMMIT;
        }

        __half* st = sKV + (it & 1) * A_STAGE;
        __half* sK = st;
        __half* sV = st + A_ARR;

        // ---- S = Q @ K^T (fp32 accum) ----
        float s[8][4];
#pragma unroll
        for (int j = 0; j < 8; j++)
#pragma unroll
            for (int e = 0; e < 4; e++) s[j][e] = 0.0f;

#pragma unroll
        for (int kc = 0; kc < 4; kc++) {
            uint32_t kb[8][2];
#pragma unroll
            for (int jj = 0; jj < 4; jj++) {
                uint32_t a = s_u32(&sK[(16 * jj + brow) * ATS + kc * 16 + bko]);
                LDSM4(kb[2*jj][0], kb[2*jj][1], kb[2*jj+1][0], kb[2*jj+1][1], a);
            }
#pragma unroll
            for (int j = 0; j < 8; j++) MMA_FP16(s[j], qf[kc], kb[j]);
        }

        // ---- row max (tree + packed fp16 quad shuffle) ----
        float mn[2];
#pragma unroll
        for (int e = 0; e < 2; e++) {
            float a0 = fmaxf(s[0][2*e], s[0][2*e+1]);
            float a1 = fmaxf(s[1][2*e], s[1][2*e+1]);
            float a2 = fmaxf(s[2][2*e], s[2][2*e+1]);
            float a3 = fmaxf(s[3][2*e], s[3][2*e+1]);
            float a4 = fmaxf(s[4][2*e], s[4][2*e+1]);
            float a5 = fmaxf(s[5][2*e], s[5][2*e+1]);
            float a6 = fmaxf(s[6][2*e], s[6][2*e+1]);
            float a7 = fmaxf(s[7][2*e], s[7][2*e+1]);
            a0 = fmaxf(a0, a1); a2 = fmaxf(a2, a3);
            a4 = fmaxf(a4, a5); a6 = fmaxf(a6, a7);
            mn[e] = fmaxf(fmaxf(a0, a2), fmaxf(a4, a6));
        }
        {
            // both rows in one packed shuffle pair (fp16 rounding is
            // consistent across lanes -> still a valid common max)
            uint32_t u = f2h2(mn[0], mn[1]);
            u = hmax2(u, __shfl_xor_sync(0xffffffffu, u, 1));
            u = hmax2(u, __shfl_xor_sync(0xffffffffu, u, 2));
            __half2 hu = *reinterpret_cast<__half2*>(&u);
            float2 fu = __half22float2(hu);
            mn[0] = fmaxf(m[0], fu.x);
            mn[1] = fmaxf(m[1], fu.y);
        }

        // ---- conditional rescale ----
        bool upd = (mn[0] > m[0]) || (mn[1] > m[1]);
        if (__any_sync(0xffffffffu, upd)) {
            float a0 = ex2f(m[0] - mn[0]);
            float a1 = ex2f(m[1] - mn[1]);
            m[0] = mn[0]; m[1] = mn[1];
            l[0] *= a0; l[1] *= a1;
#pragma unroll
            for (int j = 0; j < 8; j++) {
                o[j][0] *= a0; o[j][1] *= a0;
                o[j][2] *= a1; o[j][3] *= a1;
            }
        }

        // ---- P fragments born as fp16x2 ----
        uint32_t ph[8][2];
#pragma unroll
        for (int j = 0; j < 8; j++) {
            ph[j][0] = h2ex2(f2h2(s[j][0] - m[0], s[j][1] - m[0]));
            ph[j][1] = h2ex2(f2h2(s[j][2] - m[1], s[j][3] - m[1]));
        }

        // ---- PV with fp16 accumulators (per-tile) ----
        uint32_t ot[8][2];
#pragma unroll
        for (int j = 0; j < 8; j++) { ot[j][0] = 0u; ot[j][1] = 0u; }

#pragma unroll
        for (int kc = 0; kc < 4; kc++) {
            uint32_t pa[4] = {ph[2*kc][0], ph[2*kc][1], ph[2*kc+1][0], ph[2*kc+1][1]};
            uint32_t vb[8][2];
#pragma unroll
            for (int jj = 0; jj < 4; jj++) {
                uint32_t a = s_u32(&sV[(kc * 16 + vrow) * ATS + 16 * jj + vcol]);
                LDSM4T(vb[2*jj][0], vb[2*jj][1], vb[2*jj+1][0], vb[2*jj+1][1], a);
            }
#pragma unroll
            for (int j = 0; j < 8; j++) MMA_FP16_H(ot[j], pa, vb[j]);
        }

        // ---- l sums via HADD2 tree (after PV issue, for ILP) ----
#pragma unroll
        for (int e = 0; e < 2; e++) {
            uint32_t t01 = hadd2(ph[0][e], ph[1][e]);
            uint32_t t23 = hadd2(ph[2][e], ph[3][e]);
            uint32_t t45 = hadd2(ph[4][e], ph[5][e]);
            uint32_t t67 = hadd2(ph[6][e], ph[7][e]);
            uint32_t t03 = hadd2(t01, t23);
            uint32_t t47 = hadd2(t45, t67);
            uint32_t tt  = hadd2(t03, t47);
            __half2 hh = *reinterpret_cast<__half2*>(&tt);
            float2 ff = __half22float2(hh);
            l[e] += ff.x + ff.y;
        }

        // ---- promote tile PV result into fp32 running O ----
#pragma unroll
        for (int j = 0; j < 8; j++) {
            __half2 h0 = *reinterpret_cast<__half2*>(&ot[j][0]);
            __half2 h1 = *reinterpret_cast<__half2*>(&ot[j][1]);
            float2 f0 = __half22float2(h0);
            float2 f1 = __half22float2(h1);
            o[j][0] += f0.x; o[j][1] += f0.y;
            o[j][2] += f1.x; o[j][3] += f1.y;
        }
    }

    // ---- epilogue: quad-reduce l, normalize, write fp16 O ----
    l[0] += __shfl_xor_sync(0xffffffffu, l[0], 1);
    l[0] += __shfl_xor_sync(0xffffffffu, l[0], 2);
    l[1] += __shfl_xor_sync(0xffffffffu, l[1], 1);
    l[1] += __shfl_xor_sync(0xffffffffu, l[1], 2);

    const int r0 = q0 + 16 * wrp + g;
    const float inv0 = 1.0f / l[0];
    const float inv1 = 1.0f / l[1];
#pragma unroll
    for (int j = 0; j < 8; j++) {
        int col = h * DKH + 8 * j + 2 * t;
        size_t i0 = (size_t)b * SEQ * D_MODEL + (size_t)r0 * D_MODEL + col;
        size_t i1 = i0 + (size_t)8 * D_MODEL;
        *(uint32_t*)&O16[i0] = f2h2(o[j][0] * inv0, o[j][1] * inv0);
        *(uint32_t*)&O16[i1] = f2h2(o[j][2] * inv1, o[j][3] * inv1);
    }
}

// ============================================================================
// Launch
// ============================================================================
extern "C" void kernel_launch(void* const* d_in, const int* in_sizes, int n_in,
                              void* d_out, int out_size)
{
    (void)in_sizes; (void)n_in; (void)out_size;
    const float* x  = (const float*)d_in[0];
    const float* wq = (const float*)d_in[1];
    const float* bq = (const float*)d_in[2];
    const float* wk = (const float*)d_in[3];
    const float* bk = (const float*)d_in[4];
    const float* wv = (const float*)d_in[5];
    const float* bv = (const float*)d_in[6];
    const float* wo = (const float*)d_in[7];
    const float* bo = (const float*)d_in[8];
    float* out = (float*)d_out;

    __half *X16, *O16, *Q16, *K16, *V16, *W16;
    cudaGetSymbolAddress((void**)&X16, g_X16);
    cudaGetSymbolAddress((void**)&O16, g_O16);
    cudaGetSymbolAddress((void**)&Q16, g_Q16);
    cudaGetSymbolAddress((void**)&K16, g_K16);
    cudaGetSymbolAddress((void**)&V16, g_V16);
    cudaGetSymbolAddress((void**)&W16, g_W16);

    cudaFuncSetAttribute(attention_mma,
                         cudaFuncAttributeMaxDynamicSharedMemorySize, ATT_SMEM);
    cudaFuncSetAttribute(gemm_qkv,
                         cudaFuncAttributeMaxDynamicSharedMemorySize, GEMM_SMEM);
    cudaFuncSetAttribute(gemm_out,
                         cudaFuncAttributeMaxDynamicSharedMemorySize, GEMM_SMEM);

    const size_t WSZ = (size_t)D_MODEL * D_MODEL;

    int n4x = (MROWS * D_MODEL) / 4;
    int n4w = (int)(WSZ / 4);
    convert_h4<<<(n4x + 255) / 256, 256>>>((const float4*)x, (uint2*)X16, n4x);
    dim3 wgrid((n4w + 255) / 256, 4);
    convert_weights4<<<wgrid, 256>>>((const float4*)wq, (const float4*)wk,
                                     (const float4*)wv, (const float4*)wo,
                                     (uint2*)W16, n4w);

    // fused QKV projections
    dim3 qkvgrid(D_MODEL / 128, MROWS / 128, 3);
    gemm_qkv<<<qkvgrid, 256, GEMM_SMEM>>>(X16, W16, bq, bk, bv, Q16, K16, V16);

    // tensor-core flash attention
    dim3 agrid(SEQ / 128, BATCH * NUM_HEADS);
    attention_mma<<<agrid, 256, ATT_SMEM>>>(Q16, K16, V16, O16);

    // output projection
    dim3 ogrid(D_MODEL / 128, MROWS / 128);
    gemm_out<<<ogrid, 256, GEMM_SMEM>>>(O16, W16 + 3 * WSZ, bo, out);
}